// round 3
// baseline (speedup 1.0000x reference)
#include <cuda_runtime.h>

#define NSTATE 65536
#define BMAX   1024

// per-sample state scratch, L2-resident working set (148*2 CTAs * 256KB = 76MB)
__device__ float g_state[(size_t)BMAX * NSTATE];

// RY on register window: pairs (i, i+S). new0 = c*a0 - s*a1 ; new1 = s*a0 + c*a1
template<int S>
__device__ __forceinline__ void ryk(float* r, float c, float s) {
#pragma unroll
  for (int base = 0; base < 64; base += 2 * S) {
#pragma unroll
    for (int k = 0; k < S; k++) {
      float lo = r[base + k], hi = r[base + k + S];
      r[base + k]     = fmaf(c, lo, -(s * hi));
      r[base + k + S] = fmaf(s, lo,  (c * hi));
    }
  }
}

// CNOT: if ctrl bit C set, swap target-bit-T pair (pure register renaming after unroll)
template<int C, int T>
__device__ __forceinline__ void cnotk(float* r) {
#pragma unroll
  for (int i = 0; i < 64; i++) {
    if ((i & C) && !(i & T)) {
      float t = r[i]; r[i] = r[i | T]; r[i | T] = t;
    }
  }
}

__global__ void __launch_bounds__(256, 2)
vqc_kernel(const float* __restrict__ x, const float* __restrict__ w,
           float* __restrict__ out)
{
  extern __shared__ float sm[];
  float* tb_all = sm;              // 4 teams * 64*65 floats = 16640
  float* wc   = sm + 16640;        // [8][16] cos(w/2)
  float* wsn  = wc + 128;          // [8][16] sin(w/2)
  float* eA0  = wsn + 128;         // [16] encoding amp, bit=0
  float* eA1  = eA0 + 16;          // [16] encoding amp, bit=1
  float* AL   = eA1 + 16;          // [64] product over qubits 10..15
  float* rbuf = AL + 64;           // [16] block reduction

  const int b    = blockIdx.x;
  const int tid  = threadIdx.x;
  const int team = tid >> 6, tr = tid & 63;   // 4 teams of 64 threads
  const int lane = tid & 31, wrp = tid >> 5;
  float* st = g_state + (size_t)b * NSTATE;
  float* tb = tb_all + team * (64 * 65);

  if (tid < 128) {
    float cc, ssn; sincosf(0.5f * w[tid], &ssn, &cc);
    wc[tid] = cc; wsn[tid] = ssn;
  } else if (tid < 144) {
    int q = tid - 128;
    float cc, ssn; sincosf(0.5f * x[b * 16 + q], &ssn, &cc);
    eA0[q] = (cc - ssn) * 0.7071067811865476f;   // (cos - sin)/sqrt(2)
    eA1[q] = (cc + ssn) * 0.7071067811865476f;   // (cos + sin)/sqrt(2)
  }
  __syncthreads();
  if (tid < 64) {
    float p = 1.f;
#pragma unroll
    for (int k = 0; k < 6; k++)               // L bit k  <->  qubit 15-k
      p *= ((tid >> k) & 1) ? eA1[15 - k] : eA0[15 - k];
    AL[tid] = p;
  }
  if (tid < 16) rbuf[tid] = 0.f;
  __syncthreads();

  float acc[10];
#pragma unroll
  for (int q = 0; q < 10; q++) acc[q] = 0.f;

#pragma unroll 1
  for (int d = 0; d < 8; d++) {
    const float* lc = wc  + d * 16;
    const float* ls = wsn + d * 16;

    // ======== Pass A: qubits 10..15 (tile rows) then 0..5 (tile cols) ========
    // tile M: idx = H*1024 + M*64 + L ; element (H,L) at tb[H*65 + L]
#pragma unroll 1
    for (int g = 0; g < 4; g++) {
      const int M = g * 4 + team;
      float* base = st + M * 64;
      float r[64];
      if (d == 0) {
        // generate encoded product state directly (fuses init pass)
        float FH = 1.f;
#pragma unroll
        for (int k = 0; k < 6; k++)           // H bit k <-> qubit 5-k
          FH *= ((tr >> k) & 1) ? eA1[5 - k] : eA0[5 - k];
#pragma unroll
        for (int k = 0; k < 4; k++)           // M bit k <-> qubit 9-k
          FH *= ((M >> k) & 1) ? eA1[9 - k] : eA0[9 - k];
#pragma unroll
        for (int j = 0; j < 64; j++) r[j] = FH * AL[j];
      } else {
        // coalesced stage-in: thread tr supplies column tr of every row
#pragma unroll
        for (int j = 0; j < 64; j++) tb[j * 65 + tr] = base[j * 1024 + tr];
        __syncthreads();
#pragma unroll
        for (int j = 0; j < 64; j++) r[j] = tb[tr * 65 + j];   // row H = tr
      }
      // W3 gates (qubits 10..15); reg bit k = qubit 15-k
      cnotk<32,16>(r); cnotk<8,4>(r); cnotk<2,1>(r);   // even: (10,11)(12,13)(14,15)
      cnotk<16,8>(r);  cnotk<4,2>(r);                  // odd:  (11,12)(13,14)
      ryk<16>(r, lc[11], ls[11]);
      ryk<8> (r, lc[12], ls[12]);
      ryk<4> (r, lc[13], ls[13]);
      ryk<2> (r, lc[14], ls[14]);
      ryk<1> (r, lc[15], ls[15]);              // RY(10) deferred to pass B
#pragma unroll
      for (int j = 0; j < 64; j++) tb[tr * 65 + j] = r[j];
      __syncthreads();
      // column phase: thread tr = column L, r[j] = element (H=j, L=tr)
#pragma unroll
      for (int j = 0; j < 64; j++) r[j] = tb[j * 65 + tr];
      // W1 gates (qubits 0..5); reg bit k of H = qubit 5-k
      cnotk<32,16>(r); cnotk<8,4>(r); cnotk<2,1>(r);   // even: (0,1)(2,3)(4,5)
      cnotk<16,8>(r);  cnotk<4,2>(r);                  // odd:  (1,2)(3,4)
      ryk<32>(r, lc[0], ls[0]);
      ryk<16>(r, lc[1], ls[1]);
      ryk<8> (r, lc[2], ls[2]);
      ryk<4> (r, lc[3], ls[3]);
      ryk<2> (r, lc[4], ls[4]);                // RY(5) deferred to pass B
#pragma unroll
      for (int j = 0; j < 64; j++) base[j * 1024 + tr] = r[j];  // coalesced
      __syncthreads();
    }

    // ======== Pass B: qubits 5..10 ; idx = hi*2048 + j*32 + lo ========
#pragma unroll 1
    for (int it = 0; it < 4; it++) {
      const int hi = wrp + 8 * it;
      float* base2 = st + hi * 2048 + lane;
      float r[64];
#pragma unroll
      for (int j = 0; j < 64; j++) r[j] = base2[j * 32];        // coalesced
      // reg bit k of j = qubit 10-k
      cnotk<16,8>(r); cnotk<4,2>(r);                   // even: (6,7)(8,9)
      cnotk<32,16>(r); cnotk<8,4>(r); cnotk<2,1>(r);   // odd:  (5,6)(7,8)(9,10)
      ryk<32>(r, lc[5],  ls[5]);
      ryk<16>(r, lc[6],  ls[6]);
      ryk<8> (r, lc[7],  ls[7]);
      ryk<4> (r, lc[8],  ls[8]);
      ryk<2> (r, lc[9],  ls[9]);
      ryk<1> (r, lc[10], ls[10]);
      if (d < 7) {
#pragma unroll
        for (int j = 0; j < 64; j++) base2[j * 32] = r[j];
      } else {
        // fused readout: probs + <Z_q>, q=0..9.
        // qubits 0..4 -> hi bit (4-q); qubits 5..9 -> j bit (10-q)
        float T = 0.f, m5 = 0.f, m6 = 0.f, m7 = 0.f, m8 = 0.f, m9 = 0.f;
#pragma unroll
        for (int j = 0; j < 64; j++) {
          float p = r[j] * r[j];
          T += p;
          if (j & 32) m5 += p;
          if (j & 16) m6 += p;
          if (j & 8)  m7 += p;
          if (j & 4)  m8 += p;
          if (j & 2)  m9 += p;
        }
#pragma unroll
        for (int q = 0; q < 5; q++)
          acc[q] += ((hi >> (4 - q)) & 1) ? -T : T;
        acc[5] += T - 2.f * m5;
        acc[6] += T - 2.f * m6;
        acc[7] += T - 2.f * m7;
        acc[8] += T - 2.f * m8;
        acc[9] += T - 2.f * m9;
      }
    }
    __syncthreads();
  }

  // block reduce acc -> out[b][0..9]
#pragma unroll
  for (int q = 0; q < 10; q++) {
#pragma unroll
    for (int off = 16; off > 0; off >>= 1)
      acc[q] += __shfl_xor_sync(0xffffffffu, acc[q], off);
  }
  if (lane == 0) {
#pragma unroll
    for (int q = 0; q < 10; q++) atomicAdd(&rbuf[q], acc[q]);
  }
  __syncthreads();
  if (tid < 10) out[b * 10 + tid] = rbuf[tid];
}

extern "C" void kernel_launch(void* const* d_in, const int* in_sizes, int n_in,
                              void* d_out, int out_size) {
  const float* x = (const float*)d_in[0];     // (B, 16) f32
  const float* w = (const float*)d_in[1];     // (8, 16) f32
  float* out = (float*)d_out;                 // (B, 10) f32
  int B = in_sizes[0] / 16;
  if (B > BMAX) B = BMAX;

  const int smem_bytes = (16640 + 128 + 128 + 16 + 16 + 64 + 16) * 4;
  cudaFuncSetAttribute(vqc_kernel, cudaFuncAttributeMaxDynamicSharedMemorySize,
                       smem_bytes);
  vqc_kernel<<<B, 256, smem_bytes>>>(x, w, out);
}

// round 4
// speedup vs baseline: 1.0623x; 1.0623x over previous
#include <cuda_runtime.h>

#define NSTATE 65536
#define BMAX   1024

// per-sample state scratch; concurrent working set 296 CTAs * 256KB = 76MB -> L2-resident
__device__ float g_state[(size_t)BMAX * NSTATE];

// ---- packed f32x2 helpers ----
__device__ __forceinline__ unsigned long long pk2(float a, float b) {
  unsigned long long r;
  asm("mov.b64 %0, {%1, %2};" : "=l"(r) : "f"(a), "f"(b));
  return r;
}

// RY with stride S2 (in float2 units, S2>=1): pairs (i, i+S2) of float2
template<int S2>
__device__ __forceinline__ void ry2(float2* r, float c, float s) {
  const unsigned long long c2 = pk2(c, c), s2 = pk2(s, s), ns2 = pk2(-s, -s);
#pragma unroll
  for (int base = 0; base < 32; base += 2 * S2) {
#pragma unroll
    for (int k = 0; k < S2; k++) {
      unsigned long long lo = *(unsigned long long*)&r[base + k];
      unsigned long long hi = *(unsigned long long*)&r[base + k + S2];
      unsigned long long t1, t2, nlo, nhi;
      asm("mul.rn.f32x2 %0, %1, %2;"     : "=l"(t1)  : "l"(ns2), "l"(hi));
      asm("fma.rn.f32x2 %0, %1, %2, %3;" : "=l"(nlo) : "l"(c2),  "l"(lo), "l"(t1));
      asm("mul.rn.f32x2 %0, %1, %2;"     : "=l"(t2)  : "l"(c2),  "l"(hi));
      asm("fma.rn.f32x2 %0, %1, %2, %3;" : "=l"(nhi) : "l"(s2),  "l"(lo), "l"(t2));
      *(unsigned long long*)&r[base + k]      = nlo;
      *(unsigned long long*)&r[base + k + S2] = nhi;
    }
  }
}

// RY on adjacent floats (float stride 1): acts inside each float2
__device__ __forceinline__ void ryc(float2* r, float c, float s) {
#pragma unroll
  for (int i = 0; i < 32; i++) {
    float x = r[i].x, y = r[i].y;
    r[i].x = fmaf(c, x, -(s * y));
    r[i].y = fmaf(s, x,  (c * y));
  }
}

// CNOT in float2 index space: swap (i, i|T2) when ctrl bit set — register rename
template<int C2, int T2>
__device__ __forceinline__ void cnot2(float2* r) {
#pragma unroll
  for (int i = 0; i < 32; i++)
    if ((i & C2) && !(i & T2)) { float2 t = r[i]; r[i] = r[i | T2]; r[i | T2] = t; }
}
// CNOT with float target bit 1: swap components of float2 where ctrl set
template<int C2>
__device__ __forceinline__ void cnotc(float2* r) {
#pragma unroll
  for (int i = 0; i < 32; i++)
    if (i & C2) { float t = r[i].x; r[i].x = r[i].y; r[i].y = t; }
}

// smem: 4 teams * 64 rows * 33 float2 (pad keeps STS.64 conflict-free) = 8448 f2
#define TBF2  (64 * 33)
#define SMEM_F2 (4 * TBF2)
#define SMEM_BYTES (SMEM_F2 * 8 + (128 + 128 + 16 + 16 + 64 + 16) * 4)

__global__ void __launch_bounds__(256, 2)
vqc_kernel(const float* __restrict__ x, const float* __restrict__ w,
           float* __restrict__ out)
{
  extern __shared__ float2 sm2[];
  float2* tb_all = sm2;
  float*  wc   = (float*)(sm2 + SMEM_F2);   // [8][16] cos(w/2)
  float*  wsn  = wc + 128;                  // [8][16] sin(w/2)
  float*  eA0  = wsn + 128;                 // [16]
  float*  eA1  = eA0 + 16;                  // [16]
  float*  AL   = eA1 + 16;                  // [64] product over qubits 10..15
  float*  rbuf = AL + 64;                   // [16]

  const int b    = blockIdx.x;
  const int tid  = threadIdx.x;
  const int team = tid >> 6, tr = tid & 63;
  const int lane = tid & 31, wrp = tid >> 5;
  float*  st = g_state + (size_t)b * NSTATE;
  float2* tb = tb_all + team * TBF2;

  if (tid < 128) {
    float cc, ssn; sincosf(0.5f * w[tid], &ssn, &cc);
    wc[tid] = cc; wsn[tid] = ssn;
  } else if (tid < 144) {
    int q = tid - 128;
    float cc, ssn; sincosf(0.5f * x[b * 16 + q], &ssn, &cc);
    eA0[q] = (cc - ssn) * 0.7071067811865476f;
    eA1[q] = (cc + ssn) * 0.7071067811865476f;
  }
  __syncthreads();
  if (tid < 64) {
    float p = 1.f;
#pragma unroll
    for (int k = 0; k < 6; k++)              // L bit k <-> qubit 15-k
      p *= ((tid >> k) & 1) ? eA1[15 - k] : eA0[15 - k];
    AL[tid] = p;
  }
  if (tid < 16) rbuf[tid] = 0.f;
  __syncthreads();

  float acc[10];
#pragma unroll
  for (int q = 0; q < 10; q++) acc[q] = 0.f;

#pragma unroll 1
  for (int d = 0; d < 8; d++) {
    const float* lc = wc  + d * 16;
    const float* ls = wsn + d * 16;

    // ==== Pass A: idx = H*1024 + M*64 + L ; W3 on L bits (q10..15), W1 on H bits (q0..5)
#pragma unroll 1
    for (int g = 0; g < 4; g++) {
      const int M = g * 4 + team;
      float2 r[32];
      if (d == 0) {
        float FH = 1.f;
#pragma unroll
        for (int k = 0; k < 6; k++)          // H bit k <-> qubit 5-k
          FH *= ((tr >> k) & 1) ? eA1[5 - k] : eA0[5 - k];
#pragma unroll
        for (int k = 0; k < 4; k++)          // M bit k <-> qubit 9-k
          FH *= ((M >> k) & 1) ? eA1[9 - k] : eA0[9 - k];
#pragma unroll
        for (int i = 0; i < 32; i++)
          r[i] = make_float2(FH * AL[2 * i], FH * AL[2 * i + 1]);
      } else {
        // row H=tr is contiguous in global: 16 x LDG.128
        const float4* p = (const float4*)(st + tr * 1024 + M * 64);
#pragma unroll
        for (int q = 0; q < 16; q++) {
          float4 v = p[q];
          r[2 * q]     = make_float2(v.x, v.y);
          r[2 * q + 1] = make_float2(v.z, v.w);
        }
      }
      // W3: even (10,11)(12,13)(14,15) then odd (11,12)(13,14); L bit k = q15-k
      cnot2<16, 8>(r); cnot2<4, 2>(r); cnotc<1>(r);
      cnot2<8, 4>(r);  cnot2<2, 1>(r);
      ry2<8>(r, lc[11], ls[11]);
      ry2<4>(r, lc[12], ls[12]);
      ry2<2>(r, lc[13], ls[13]);
      ry2<1>(r, lc[14], ls[14]);
      ryc  (r, lc[15], ls[15]);              // RY(10) deferred to pass B
      // transpose via smem: write row tr
      float2* row = tb + tr * 33;
#pragma unroll
      for (int i = 0; i < 32; i++) row[i] = r[i];
      __syncthreads();
      // read column L=tr: register index = H value j
      const float* tbf = (const float*)tb;
#pragma unroll
      for (int j = 0; j < 32; j++) {
        r[j].x = tbf[(2 * j)     * 66 + tr];
        r[j].y = tbf[(2 * j + 1) * 66 + tr];
      }
      // W1: even (0,1)(2,3)(4,5) then odd (1,2)(3,4); H bit k = q5-k
      cnot2<16, 8>(r); cnot2<4, 2>(r); cnotc<1>(r);
      cnot2<8, 4>(r);  cnot2<2, 1>(r);
      ry2<16>(r, lc[0], ls[0]);
      ry2<8> (r, lc[1], ls[1]);
      ry2<4> (r, lc[2], ls[2]);
      ry2<2> (r, lc[3], ls[3]);
      ry2<1> (r, lc[4], ls[4]);              // RY(5) deferred to pass B
      // store column coalesced (consecutive tr -> consecutive addresses)
      float* baseo = st + M * 64 + tr;
#pragma unroll
      for (int j = 0; j < 32; j++) {
        baseo[(2 * j)     * 1024] = r[j].x;
        baseo[(2 * j + 1) * 1024] = r[j].y;
      }
      __syncthreads();
    }

    // ==== Pass B: idx = hi*2048 + j*32 + lo ; gates on j bits (q5..10)
#pragma unroll 1
    for (int it = 0; it < 4; it++) {
      const int hi = wrp + 8 * it;
      float* base2 = st + hi * 2048 + lane;
      float2 r[32];
#pragma unroll
      for (int j = 0; j < 32; j++) {
        r[j].x = base2[(2 * j)     * 32];
        r[j].y = base2[(2 * j + 1) * 32];
      }
      // even (6,7)(8,9) then odd (5,6)(7,8)(9,10); j bit k = q10-k
      cnot2<8, 4>(r);  cnot2<2, 1>(r);
      cnot2<16, 8>(r); cnot2<4, 2>(r); cnotc<1>(r);
      ry2<16>(r, lc[5],  ls[5]);
      ry2<8> (r, lc[6],  ls[6]);
      ry2<4> (r, lc[7],  ls[7]);
      ry2<2> (r, lc[8],  ls[8]);
      ry2<1> (r, lc[9],  ls[9]);
      ryc    (r, lc[10], ls[10]);
      if (d < 7) {
#pragma unroll
        for (int j = 0; j < 32; j++) {
          base2[(2 * j)     * 32] = r[j].x;
          base2[(2 * j + 1) * 32] = r[j].y;
        }
      } else {
        // fused readout. q0..4 from hi bits; q5..9 from float2-index bits 16,8,4,2,1
        float T = 0.f, m5 = 0.f, m6 = 0.f, m7 = 0.f, m8 = 0.f, m9 = 0.f;
#pragma unroll
        for (int i = 0; i < 32; i++) {
          float p = fmaf(r[i].x, r[i].x, r[i].y * r[i].y);
          T += p;
          if (i & 16) m5 += p;
          if (i & 8)  m6 += p;
          if (i & 4)  m7 += p;
          if (i & 2)  m8 += p;
          if (i & 1)  m9 += p;
        }
#pragma unroll
        for (int q = 0; q < 5; q++)
          acc[q] += ((hi >> (4 - q)) & 1) ? -T : T;
        acc[5] += T - 2.f * m5;
        acc[6] += T - 2.f * m6;
        acc[7] += T - 2.f * m7;
        acc[8] += T - 2.f * m8;
        acc[9] += T - 2.f * m9;
      }
    }
    __syncthreads();
  }

  // block reduce -> out[b][0..9]
#pragma unroll
  for (int q = 0; q < 10; q++) {
#pragma unroll
    for (int off = 16; off > 0; off >>= 1)
      acc[q] += __shfl_xor_sync(0xffffffffu, acc[q], off);
  }
  if (lane == 0) {
#pragma unroll
    for (int q = 0; q < 10; q++) atomicAdd(&rbuf[q], acc[q]);
  }
  __syncthreads();
  if (tid < 10) out[b * 10 + tid] = rbuf[tid];
}

extern "C" void kernel_launch(void* const* d_in, const int* in_sizes, int n_in,
                              void* d_out, int out_size) {
  const float* x = (const float*)d_in[0];   // (B, 16) f32
  const float* w = (const float*)d_in[1];   // (8, 16) f32
  float* out = (float*)d_out;               // (B, 10) f32
  int B = in_sizes[0] / 16;
  if (B > BMAX) B = BMAX;

  cudaFuncSetAttribute(vqc_kernel, cudaFuncAttributeMaxDynamicSharedMemorySize,
                       SMEM_BYTES);
  vqc_kernel<<<B, 256, SMEM_BYTES>>>(x, w, out);
}

// round 5
// speedup vs baseline: 1.0638x; 1.0014x over previous
#include <cuda_runtime.h>

#define NSTATE 65536
#define BMAX   1024

// per-sample state scratch; concurrent working set 296 CTAs * 256KB = 76MB -> L2-resident
__device__ float g_state[(size_t)BMAX * NSTATE];

// ---- packed f32x2 helpers ----
__device__ __forceinline__ unsigned long long pk2(float a, float b) {
  unsigned long long r;
  asm("mov.b64 %0, {%1, %2};" : "=l"(r) : "f"(a), "f"(b));
  return r;
}

// RY with stride S2 (in float2 units, S2>=1): pairs (i, i+S2) of float2
template<int S2>
__device__ __forceinline__ void ry2(float2* r, float c, float s) {
  const unsigned long long c2 = pk2(c, c), s2 = pk2(s, s), ns2 = pk2(-s, -s);
#pragma unroll
  for (int base = 0; base < 32; base += 2 * S2) {
#pragma unroll
    for (int k = 0; k < S2; k++) {
      unsigned long long lo = *(unsigned long long*)&r[base + k];
      unsigned long long hi = *(unsigned long long*)&r[base + k + S2];
      unsigned long long t1, t2, nlo, nhi;
      asm("mul.rn.f32x2 %0, %1, %2;"     : "=l"(t1)  : "l"(ns2), "l"(hi));
      asm("fma.rn.f32x2 %0, %1, %2, %3;" : "=l"(nlo) : "l"(c2),  "l"(lo), "l"(t1));
      asm("mul.rn.f32x2 %0, %1, %2;"     : "=l"(t2)  : "l"(c2),  "l"(hi));
      asm("fma.rn.f32x2 %0, %1, %2, %3;" : "=l"(nhi) : "l"(s2),  "l"(lo), "l"(t2));
      *(unsigned long long*)&r[base + k]      = nlo;
      *(unsigned long long*)&r[base + k + S2] = nhi;
    }
  }
}

// RY on adjacent floats (float stride 1): acts inside each float2
__device__ __forceinline__ void ryc(float2* r, float c, float s) {
#pragma unroll
  for (int i = 0; i < 32; i++) {
    float x = r[i].x, y = r[i].y;
    r[i].x = fmaf(c, x, -(s * y));
    r[i].y = fmaf(s, x,  (c * y));
  }
}

// CNOT in float2 index space: swap (i, i|T2) when ctrl bit set — register rename
template<int C2, int T2>
__device__ __forceinline__ void cnot2(float2* r) {
#pragma unroll
  for (int i = 0; i < 32; i++)
    if ((i & C2) && !(i & T2)) { float2 t = r[i]; r[i] = r[i | T2]; r[i | T2] = t; }
}
// CNOT with float target bit 1: swap components of float2 where ctrl set
template<int C2>
__device__ __forceinline__ void cnotc(float2* r) {
#pragma unroll
  for (int i = 0; i < 32; i++)
    if (i & C2) { float t = r[i].x; r[i].x = r[i].y; r[i].y = t; }
}

// smem: 4 teams * 64 rows * 33 float2 (pad keeps STS.64 conflict-free) = 8448 f2
#define TBF2  (64 * 33)
#define SMEM_F2 (4 * TBF2)
#define SMEM_BYTES (SMEM_F2 * 8 + (128 + 128 + 16 + 16 + 64 + 16) * 4)

__global__ void __launch_bounds__(256, 2)
vqc_kernel(const float* __restrict__ x, const float* __restrict__ w,
           float* __restrict__ out)
{
  extern __shared__ float2 sm2[];
  float2* tb_all = sm2;
  float*  wc   = (float*)(sm2 + SMEM_F2);   // [8][16] cos(w/2)
  float*  wsn  = wc + 128;                  // [8][16] sin(w/2)
  float*  eA0  = wsn + 128;                 // [16]
  float*  eA1  = eA0 + 16;                  // [16]
  float*  AL   = eA1 + 16;                  // [64] product over qubits 10..15
  float*  rbuf = AL + 64;                   // [16]

  const int b    = blockIdx.x;
  const int tid  = threadIdx.x;
  const int team = tid >> 6, tr = tid & 63;
  const int lane = tid & 31, wrp = tid >> 5;
  float*  st = g_state + (size_t)b * NSTATE;
  float2* tb = tb_all + team * TBF2;

  if (tid < 128) {
    float cc, ssn; sincosf(0.5f * w[tid], &ssn, &cc);
    wc[tid] = cc; wsn[tid] = ssn;
  } else if (tid < 144) {
    int q = tid - 128;
    float cc, ssn; sincosf(0.5f * x[b * 16 + q], &ssn, &cc);
    eA0[q] = (cc - ssn) * 0.7071067811865476f;
    eA1[q] = (cc + ssn) * 0.7071067811865476f;
  }
  __syncthreads();
  if (tid < 64) {
    float p = 1.f;
#pragma unroll
    for (int k = 0; k < 6; k++)              // L bit k <-> qubit 15-k
      p *= ((tid >> k) & 1) ? eA1[15 - k] : eA0[15 - k];
    AL[tid] = p;
  }
  if (tid < 16) rbuf[tid] = 0.f;
  __syncthreads();

  float acc[10];
#pragma unroll
  for (int q = 0; q < 10; q++) acc[q] = 0.f;

#pragma unroll 1
  for (int d = 0; d < 8; d++) {
    const float* lc = wc  + d * 16;
    const float* ls = wsn + d * 16;

    // ==== Pass A: idx = H*1024 + M*64 + L ; W3 on L bits (q10..15), W1 on H bits (q0..5)
#pragma unroll 1
    for (int g = 0; g < 4; g++) {
      const int M = g * 4 + team;
      float2 r[32];
      if (d == 0) {
        float FH = 1.f;
#pragma unroll
        for (int k = 0; k < 6; k++)          // H bit k <-> qubit 5-k
          FH *= ((tr >> k) & 1) ? eA1[5 - k] : eA0[5 - k];
#pragma unroll
        for (int k = 0; k < 4; k++)          // M bit k <-> qubit 9-k
          FH *= ((M >> k) & 1) ? eA1[9 - k] : eA0[9 - k];
#pragma unroll
        for (int i = 0; i < 32; i++)
          r[i] = make_float2(FH * AL[2 * i], FH * AL[2 * i + 1]);
      } else {
        // row H=tr is contiguous in global: 16 x LDG.128
        const float4* p = (const float4*)(st + tr * 1024 + M * 64);
#pragma unroll
        for (int q = 0; q < 16; q++) {
          float4 v = p[q];
          r[2 * q]     = make_float2(v.x, v.y);
          r[2 * q + 1] = make_float2(v.z, v.w);
        }
      }
      // W3: even (10,11)(12,13)(14,15) then odd (11,12)(13,14); L bit k = q15-k
      cnot2<16, 8>(r); cnot2<4, 2>(r); cnotc<1>(r);
      cnot2<8, 4>(r);  cnot2<2, 1>(r);
      ry2<8>(r, lc[11], ls[11]);
      ry2<4>(r, lc[12], ls[12]);
      ry2<2>(r, lc[13], ls[13]);
      ry2<1>(r, lc[14], ls[14]);
      ryc  (r, lc[15], ls[15]);              // RY(10) deferred to pass B
      // transpose via smem: write row tr
      float2* row = tb + tr * 33;
#pragma unroll
      for (int i = 0; i < 32; i++) row[i] = r[i];
      __syncthreads();
      // read column L=tr: register index = H value j
      const float* tbf = (const float*)tb;
#pragma unroll
      for (int j = 0; j < 32; j++) {
        r[j].x = tbf[(2 * j)     * 66 + tr];
        r[j].y = tbf[(2 * j + 1) * 66 + tr];
      }
      // W1: even (0,1)(2,3)(4,5) then odd (1,2)(3,4); H bit k = q5-k
      cnot2<16, 8>(r); cnot2<4, 2>(r); cnotc<1>(r);
      cnot2<8, 4>(r);  cnot2<2, 1>(r);
      ry2<16>(r, lc[0], ls[0]);
      ry2<8> (r, lc[1], ls[1]);
      ry2<4> (r, lc[2], ls[2]);
      ry2<2> (r, lc[3], ls[3]);
      ry2<1> (r, lc[4], ls[4]);              // RY(5) deferred to pass B
      // store column coalesced (consecutive tr -> consecutive addresses)
      float* baseo = st + M * 64 + tr;
#pragma unroll
      for (int j = 0; j < 32; j++) {
        baseo[(2 * j)     * 1024] = r[j].x;
        baseo[(2 * j + 1) * 1024] = r[j].y;
      }
      __syncthreads();
    }

    // ==== Pass B: idx = hi*2048 + j*32 + lo ; gates on j bits (q5..10)
#pragma unroll 1
    for (int it = 0; it < 4; it++) {
      const int hi = wrp + 8 * it;
      float* base2 = st + hi * 2048 + lane;
      float2 r[32];
#pragma unroll
      for (int j = 0; j < 32; j++) {
        r[j].x = base2[(2 * j)     * 32];
        r[j].y = base2[(2 * j + 1) * 32];
      }
      // even (6,7)(8,9) then odd (5,6)(7,8)(9,10); j bit k = q10-k
      cnot2<8, 4>(r);  cnot2<2, 1>(r);
      cnot2<16, 8>(r); cnot2<4, 2>(r); cnotc<1>(r);
      ry2<16>(r, lc[5],  ls[5]);
      ry2<8> (r, lc[6],  ls[6]);
      ry2<4> (r, lc[7],  ls[7]);
      ry2<2> (r, lc[8],  ls[8]);
      ry2<1> (r, lc[9],  ls[9]);
      ryc    (r, lc[10], ls[10]);
      if (d < 7) {
#pragma unroll
        for (int j = 0; j < 32; j++) {
          base2[(2 * j)     * 32] = r[j].x;
          base2[(2 * j + 1) * 32] = r[j].y;
        }
      } else {
        // fused readout. q0..4 from hi bits; q5..9 from float2-index bits 16,8,4,2,1
        float T = 0.f, m5 = 0.f, m6 = 0.f, m7 = 0.f, m8 = 0.f, m9 = 0.f;
#pragma unroll
        for (int i = 0; i < 32; i++) {
          float p = fmaf(r[i].x, r[i].x, r[i].y * r[i].y);
          T += p;
          if (i & 16) m5 += p;
          if (i & 8)  m6 += p;
          if (i & 4)  m7 += p;
          if (i & 2)  m8 += p;
          if (i & 1)  m9 += p;
        }
#pragma unroll
        for (int q = 0; q < 5; q++)
          acc[q] += ((hi >> (4 - q)) & 1) ? -T : T;
        acc[5] += T - 2.f * m5;
        acc[6] += T - 2.f * m6;
        acc[7] += T - 2.f * m7;
        acc[8] += T - 2.f * m8;
        acc[9] += T - 2.f * m9;
      }
    }
    __syncthreads();
  }

  // block reduce -> out[b][0..9]
#pragma unroll
  for (int q = 0; q < 10; q++) {
#pragma unroll
    for (int off = 16; off > 0; off >>= 1)
      acc[q] += __shfl_xor_sync(0xffffffffu, acc[q], off);
  }
  if (lane == 0) {
#pragma unroll
    for (int q = 0; q < 10; q++) atomicAdd(&rbuf[q], acc[q]);
  }
  __syncthreads();
  if (tid < 10) out[b * 10 + tid] = rbuf[tid];
}

extern "C" void kernel_launch(void* const* d_in, const int* in_sizes, int n_in,
                              void* d_out, int out_size) {
  const float* x = (const float*)d_in[0];   // (B, 16) f32
  const float* w = (const float*)d_in[1];   // (8, 16) f32
  float* out = (float*)d_out;               // (B, 10) f32
  int B = in_sizes[0] / 16;
  if (B > BMAX) B = BMAX;

  cudaFuncSetAttribute(vqc_kernel, cudaFuncAttributeMaxDynamicSharedMemorySize,
                       SMEM_BYTES);
  vqc_kernel<<<B, 256, SMEM_BYTES>>>(x, w, out);
}

// round 6
// speedup vs baseline: 1.5896x; 1.4943x over previous
#include <cuda_runtime.h>

#define NSTATE 65536
#define BMAX   1024

__device__ __align__(16) float g_state[(size_t)BMAX * NSTATE];

__device__ __forceinline__ unsigned long long pk2(float a, float b) {
  unsigned long long r;
  asm("mov.b64 %0, {%1, %2};" : "=l"(r) : "f"(a), "f"(b));
  return r;
}

template<int S2>
__device__ __forceinline__ void ry2(float2* r, float c, float s) {
  const unsigned long long c2 = pk2(c, c), s2 = pk2(s, s), ns2 = pk2(-s, -s);
#pragma unroll
  for (int base = 0; base < 32; base += 2 * S2)
#pragma unroll
    for (int k = 0; k < S2; k++) {
      unsigned long long lo = *(unsigned long long*)&r[base + k];
      unsigned long long hi = *(unsigned long long*)&r[base + k + S2];
      unsigned long long t1, t2, nlo, nhi;
      asm("mul.rn.f32x2 %0, %1, %2;"     : "=l"(t1)  : "l"(ns2), "l"(hi));
      asm("fma.rn.f32x2 %0, %1, %2, %3;" : "=l"(nlo) : "l"(c2),  "l"(lo), "l"(t1));
      asm("mul.rn.f32x2 %0, %1, %2;"     : "=l"(t2)  : "l"(c2),  "l"(hi));
      asm("fma.rn.f32x2 %0, %1, %2, %3;" : "=l"(nhi) : "l"(s2),  "l"(lo), "l"(t2));
      *(unsigned long long*)&r[base + k]      = nlo;
      *(unsigned long long*)&r[base + k + S2] = nhi;
    }
}

__device__ __forceinline__ void ryc(float2* r, float c, float s) {
#pragma unroll
  for (int i = 0; i < 32; i++) {
    float x = r[i].x, y = r[i].y;
    r[i].x = fmaf(c, x, -(s * y));
    r[i].y = fmaf(s, x,  (c * y));
  }
}

template<int C2, int T2>
__device__ __forceinline__ void cnot2(float2* r) {
#pragma unroll
  for (int i = 0; i < 32; i++)
    if ((i & C2) && !(i & T2)) { float2 t = r[i]; r[i] = r[i | T2]; r[i | T2] = t; }
}
template<int C2>
__device__ __forceinline__ void cnotc(float2* r) {
#pragma unroll
  for (int i = 0; i < 32; i++)
    if (i & C2) { float t = r[i].x; r[i].x = r[i].y; r[i].y = t; }
}

#define TILE_F   2176                 // 32 rows * 68 floats (pad 4/row)
#define TILES_F  (8 * TILE_F)
#define SMEM_FLOATS (TILES_F + 128 + 128 + 16 + 16 + 64 + 64 + 16 + 16)
#define SMEM_BYTES  (SMEM_FLOATS * 4)

__global__ void __launch_bounds__(256, 2)
vqc_kernel(const float* __restrict__ x, const float* __restrict__ w,
           float* __restrict__ out)
{
  extern __shared__ float sm[];
  float* tiles = sm;
  float* wc  = sm + TILES_F;      // [8][16] cos(w/2)
  float* ws  = wc + 128;          // [8][16] sin(w/2)
  float* eA0 = ws + 128;          // [16]
  float* eA1 = eA0 + 16;          // [16]
  float* chi = eA1 + 16;          // [64] q0..5 factor after layer-0 pass-1 gates
  float* psi = chi + 64;          // [64] q10..15 factor after layer-0 L gates
  float* PM  = psi + 64;          // [16] q6..9 product
  float* rbuf = PM + 16;          // [16]

  const int b = blockIdx.x, tid = threadIdx.x;
  const int lane = tid & 31, wid = tid >> 5;
  float* st     = g_state + (size_t)b * NSTATE;
  float* mytile = tiles + wid * TILE_F;

  if (tid < 128) {
    float c, s; sincosf(0.5f * w[tid], &s, &c);
    wc[tid] = c; ws[tid] = s;
  } else if (tid < 144) {
    int q = tid - 128;
    float c, s; sincosf(0.5f * x[b * 16 + q], &s, &c);
    eA0[q] = (c - s) * 0.7071067811865476f;
    eA1[q] = (c + s) * 0.7071067811865476f;
  }
  if (tid < 16) rbuf[tid] = 0.f;
  __syncthreads();

  // product factors: chi bit5=q0..bit0=q5 ; psi bit5=q10..bit0=q15 ; PM bit3=q6..bit0=q9
  if (tid < 64) {
    float p = 1.f, p2 = 1.f;
#pragma unroll
    for (int k = 0; k < 6; k++) {
      int bit = (tid >> (5 - k)) & 1;
      p  *= bit ? eA1[k]      : eA0[k];
      p2 *= bit ? eA1[10 + k] : eA0[10 + k];
    }
    chi[tid] = p; psi[tid] = p2;
  }
  if (tid < 16) {
    float p = ((tid & 8) ? eA1[6] : eA0[6]) * ((tid & 4) ? eA1[7] : eA0[7])
            * ((tid & 2) ? eA1[8] : eA0[8]) * ((tid & 1) ? eA1[9] : eA0[9]);
    PM[tid] = p;
  }
  __syncthreads();

  // layer-0 gates on chi (E(0,1)(2,3)(4,5); O(1,2)(3,4); RY(0..4))
  // and psi (E(10,11)(12,13)(14,15); O(11,12)(13,14); RY(11..15)) — same masks
  {
    float vc = 0.f, vp = 0.f;
    if (tid < 64) {
      int g = tid;
      if (g & 16) g ^= 8;  if (g & 4)  g ^= 2;     // odd CNOTs (inverse gather)
      if (g & 32) g ^= 16; if (g & 8)  g ^= 4; if (g & 2) g ^= 1;  // even CNOTs
      vc = chi[g]; vp = psi[g];
    }
    __syncthreads();
    if (tid < 64) { chi[tid] = vc; psi[tid] = vp; }
    __syncthreads();
#pragma unroll 1
    for (int k = 0; k < 5; k++) {
      const int mA = 32 >> k, mB = 16 >> k;
      const float cA = wc[k], sA = ws[k], cB = wc[11 + k], sB = ws[11 + k];
      float a1 = 0.f, b1 = 0.f, a2 = 0.f, b2 = 0.f;
      if (tid < 64) { a1 = chi[tid]; b1 = chi[tid ^ mA]; a2 = psi[tid]; b2 = psi[tid ^ mB]; }
      __syncthreads();
      if (tid < 64) {
        chi[tid] = (tid & mA) ? fmaf(cA, a1, sA * b1) : fmaf(cA, a1, -(sA * b1));
        psi[tid] = (tid & mB) ? fmaf(cB, a2, sB * b2) : fmaf(cB, a2, -(sB * b2));
      }
      __syncthreads();
    }
  }

  float acc[10];
#pragma unroll
  for (int q = 0; q < 10; q++) acc[q] = 0.f;

#pragma unroll 1
  for (int d = 0; d < 8; d++) {
    const float* lc = wc + d * 16;
    const float* ls = ws + d * 16;

    // ===== Pass 1: q0..5 (idx bits 15..10); fixed low bits c; fully coalesced =====
    if (d > 0) {
#pragma unroll 1
      for (int it = 0; it < 4; it++) {
        float* base = st + it * 256 + tid;
        float2 r[32];              // fi: q0=16,q1=8,q2=4,q3=2,q4=1 ; comp=q5
#pragma unroll
        for (int j = 0; j < 32; j++) {
          r[j].x = base[(2 * j) * 1024];
          r[j].y = base[(2 * j + 1) * 1024];
        }
        cnot2<16, 8>(r); cnot2<4, 2>(r); cnotc<1>(r);   // E(0,1)(2,3)(4,5)
        cnot2<8, 4>(r);  cnot2<2, 1>(r);                // O(1,2)(3,4)
        ry2<16>(r, lc[0], ls[0]);
        ry2<8> (r, lc[1], ls[1]);
        ry2<4> (r, lc[2], ls[2]);
        ry2<2> (r, lc[3], ls[3]);
        ry2<1> (r, lc[4], ls[4]);                       // RY(5) deferred to M
#pragma unroll
        for (int j = 0; j < 32; j++) {
          base[(2 * j) * 1024]     = r[j].x;
          base[(2 * j + 1) * 1024] = r[j].y;
        }
      }
      __syncthreads();
    }

    // ===== Pass 2: per-warp 8KB supertile, idx bits 10..0 ; s = bits 15..11 (q0..4) =====
#pragma unroll 1
    for (int it = 0; it < 4; it++) {
      const int s = it * 8 + wid;
      float2 m2[32];               // fi: q5=16,q6=8,q7=4,q8=2,q9=1 ; comp=q10
      if (d == 0) {
        const float C0 = chi[2 * s], C1 = chi[2 * s + 1];
        const float p0 = psi[lane], p1 = psi[32 + lane];
#pragma unroll
        for (int fj = 0; fj < 32; fj++) {
          float bse = ((fj & 16) ? C1 : C0) * PM[fj & 15];
          m2[fj] = make_float2(bse * p0, bse * p1);
        }
      } else {
        const float4* g4 = (const float4*)(st + s * 2048);
#pragma unroll
        for (int i = 0; i < 16; i++) {
          float4 v = g4[i * 32 + lane];
          *(float4*)(mytile + 136 * i + 4 * lane + 4 * (lane >> 4)) = v;
        }
        __syncwarp();
        if (d < 7) {
          // L phase: row = lane (q5..9 bits); fi: q10=16,q11=8,q12=4,q13=2,q14=1 ; comp=q15
          float2 r[32];
#pragma unroll
          for (int k = 0; k < 16; k++) {
            float4 v = *(const float4*)(mytile + 68 * lane + 4 * k);
            r[2 * k]     = make_float2(v.x, v.y);
            r[2 * k + 1] = make_float2(v.z, v.w);
          }
          cnot2<16, 8>(r); cnot2<4, 2>(r); cnotc<1>(r); // E(10,11)(12,13)(14,15)
          cnot2<8, 4>(r);  cnot2<2, 1>(r);              // O(11,12)(13,14)
          ry2<8>(r, lc[11], ls[11]);
          ry2<4>(r, lc[12], ls[12]);
          ry2<2>(r, lc[13], ls[13]);
          ry2<1>(r, lc[14], ls[14]);
          ryc   (r, lc[15], ls[15]);                    // RY(10) deferred to M
#pragma unroll
          for (int k = 0; k < 16; k++)
            *(float4*)(mytile + 68 * lane + 4 * k) =
              make_float4(r[2 * k].x, r[2 * k].y, r[2 * k + 1].x, r[2 * k + 1].y);
          __syncwarp();
#pragma unroll
          for (int fj = 0; fj < 32; fj++) {
            m2[fj].x = mytile[68 * fj + lane];
            m2[fj].y = mytile[68 * fj + 32 + lane];
          }
        } else {
          // layer 7: only CNOT(10,11) survives of the L group -> fold into addressing
#pragma unroll
          for (int fj = 0; fj < 32; fj++) {
            m2[fj].x = mytile[68 * fj + lane];
            m2[fj].y = mytile[68 * fj + 32 + (lane ^ 16)];
          }
        }
      }
      // M gates (q5..10)
      cnot2<8, 4>(m2); cnot2<2, 1>(m2);                 // E(6,7)(8,9)
      cnot2<16, 8>(m2); cnot2<4, 2>(m2); cnotc<1>(m2);  // O(5,6)(7,8)(9,10)
      ry2<16>(m2, lc[5], ls[5]);
      ry2<8> (m2, lc[6], ls[6]);
      ry2<4> (m2, lc[7], ls[7]);
      ry2<2> (m2, lc[8], ls[8]);
      ry2<1> (m2, lc[9], ls[9]);
      ryc    (m2, lc[10], ls[10]);
      if (d < 7) {
        float* o = st + s * 2048 + lane;
#pragma unroll
        for (int fj = 0; fj < 32; fj++) {
          o[(2 * fj) * 32]     = m2[fj].x;
          o[(2 * fj + 1) * 32] = m2[fj].y;
        }
      } else {
        float T = 0.f, m5 = 0.f, m6 = 0.f, m7 = 0.f, m8 = 0.f, m9 = 0.f;
#pragma unroll
        for (int i = 0; i < 32; i++) {
          float p = fmaf(m2[i].x, m2[i].x, m2[i].y * m2[i].y);
          T += p;
          if (i & 16) m5 += p;
          if (i & 8)  m6 += p;
          if (i & 4)  m7 += p;
          if (i & 2)  m8 += p;
          if (i & 1)  m9 += p;
        }
#pragma unroll
        for (int q = 0; q < 5; q++)
          acc[q] += ((s >> (4 - q)) & 1) ? -T : T;
        acc[5] += T - 2.f * m5;
        acc[6] += T - 2.f * m6;
        acc[7] += T - 2.f * m7;
        acc[8] += T - 2.f * m8;
        acc[9] += T - 2.f * m9;
      }
    }
    __syncthreads();
  }

  // reduce acc (over lanes = q11..15 and warps) -> out[b][0..9]
#pragma unroll
  for (int q = 0; q < 10; q++)
#pragma unroll
    for (int off = 16; off > 0; off >>= 1)
      acc[q] += __shfl_xor_sync(0xffffffffu, acc[q], off);
  if (lane == 0)
#pragma unroll
    for (int q = 0; q < 10; q++) atomicAdd(&rbuf[q], acc[q]);
  __syncthreads();
  if (tid < 10) out[b * 10 + tid] = rbuf[tid];
}

extern "C" void kernel_launch(void* const* d_in, const int* in_sizes, int n_in,
                              void* d_out, int out_size) {
  const float* x = (const float*)d_in[0];
  const float* w = (const float*)d_in[1];
  float* out = (float*)d_out;
  int B = in_sizes[0] / 16;
  if (B > BMAX) B = BMAX;
  cudaFuncSetAttribute(vqc_kernel, cudaFuncAttributeMaxDynamicSharedMemorySize,
                       SMEM_BYTES);
  vqc_kernel<<<B, 256, SMEM_BYTES>>>(x, w, out);
}